// round 1
// baseline (speedup 1.0000x reference)
#include <cuda_runtime.h>
#include <math.h>

#define T_TOK 4096
#define H_DIM 768
#define I_DIM 1152
#define TWO_I 2304
#define E_NUM 8

// ---------------- scratch (device globals; no cudaMalloc allowed) ----------
__device__ int   g_count[E_NUM];
__device__ int   g_tok[E_NUM * T_TOK];     // token index per (expert, pos)
__device__ int   g_dst[E_NUM * T_TOK];     // dest slot = 2*t + k
__device__ float g_w  [E_NUM * T_TOK];     // routing weight per slot
__device__ float g_h1 [(size_t)E_NUM * T_TOK * TWO_I];   // expert up-proj raw
__device__ float g_act[(size_t)E_NUM * T_TOK * I_DIM];   // expert activated
__device__ float g_par[(size_t)T_TOK * 2 * H_DIM];       // per-(t,k) down-proj
__device__ float g_sh [(size_t)T_TOK * TWO_I];           // shared up raw
__device__ float g_as [(size_t)T_TOK * I_DIM];           // shared activated

// ---------------- gating --------------------------------------------------
__global__ void zero_counts_kernel() {
    if (threadIdx.x < E_NUM) g_count[threadIdx.x] = 0;
}

__global__ void gating_kernel(const float* __restrict__ x,
                              const float* __restrict__ gate_w,
                              const float* __restrict__ bias) {
    __shared__ float sgw[E_NUM * H_DIM];
    int tid = threadIdx.x;
    for (int i = tid; i < E_NUM * H_DIM; i += 256) sgw[i] = gate_w[i];
    __syncthreads();

    int warp = tid >> 5, lane = tid & 31;
    int t = blockIdx.x * 8 + warp;
    const float* xr = x + (size_t)t * H_DIM;

    float acc[E_NUM];
#pragma unroll
    for (int e = 0; e < E_NUM; e++) acc[e] = 0.f;
    for (int h = lane; h < H_DIM; h += 32) {
        float xv = xr[h];
#pragma unroll
        for (int e = 0; e < E_NUM; e++) acc[e] += xv * sgw[e * H_DIM + h];
    }
#pragma unroll
    for (int e = 0; e < E_NUM; e++) {
        float v = acc[e];
#pragma unroll
        for (int o = 16; o > 0; o >>= 1) v += __shfl_down_sync(0xffffffffu, v, o);
        acc[e] = v;
    }
    if (lane == 0) {
        float logit[E_NUM];
#pragma unroll
        for (int e = 0; e < E_NUM; e++) logit[e] = 1.f / (1.f + expf(-acc[e]));
        int i0 = 0; float b0 = -1e30f;
#pragma unroll
        for (int e = 0; e < E_NUM; e++) {
            float s = logit[e] + bias[e];
            if (s > b0) { b0 = s; i0 = e; }
        }
        int i1 = 0; float b1 = -1e30f;
#pragma unroll
        for (int e = 0; e < E_NUM; e++) {
            if (e == i0) continue;
            float s = logit[e] + bias[e];
            if (s > b1) { b1 = s; i1 = e; }
        }
        float w0 = logit[i0], w1 = logit[i1];
        float inv = 1.f / (w0 + w1);
        w0 *= inv; w1 *= inv;
        int p0 = atomicAdd(&g_count[i0], 1);
        g_tok[i0 * T_TOK + p0] = t; g_dst[i0 * T_TOK + p0] = 2 * t;     g_w[i0 * T_TOK + p0] = w0;
        int p1 = atomicAdd(&g_count[i1], 1);
        g_tok[i1 * T_TOK + p1] = t; g_dst[i1 * T_TOK + p1] = 2 * t + 1; g_w[i1 * T_TOK + p1] = w1;
    }
}

// ---------------- dense SGEMM (NT): C[m][n] = sum_k A[m][k]*B[n][k] --------
// BM=BN=128, BK=8, 256 threads, 8x8 per thread
__global__ void __launch_bounds__(256)
sgemm_nt(const float* __restrict__ A, const float* __restrict__ B,
         float* __restrict__ C, int N, int Kd) {
    __shared__ float As[8][128];
    __shared__ float Bs[8][128];
    int tid = threadIdx.x;
    int bn = blockIdx.x * 128, bm = blockIdx.y * 128;
    int irA = tid >> 1, icA = (tid & 1) * 4;   // A: 128 rows x 8 k
    int irB = tid >> 1, icB = (tid & 1) * 4;   // B: 128 n-rows x 8 k
    int tx = tid & 15, ty = tid >> 4;

    float acc[8][8];
#pragma unroll
    for (int i = 0; i < 8; i++)
#pragma unroll
        for (int j = 0; j < 8; j++) acc[i][j] = 0.f;

    const float* Ap = A + (size_t)(bm + irA) * Kd + icA;
    const float* Bp = B + (size_t)(bn + irB) * Kd + icB;

    for (int kk = 0; kk < Kd; kk += 8) {
        float4 av = *(const float4*)(Ap + kk);
        As[icA + 0][irA] = av.x; As[icA + 1][irA] = av.y;
        As[icA + 2][irA] = av.z; As[icA + 3][irA] = av.w;
        float4 bv = *(const float4*)(Bp + kk);
        Bs[icB + 0][irB] = bv.x; Bs[icB + 1][irB] = bv.y;
        Bs[icB + 2][irB] = bv.z; Bs[icB + 3][irB] = bv.w;
        __syncthreads();
#pragma unroll
        for (int k = 0; k < 8; k++) {
            float4 a0 = *(float4*)&As[k][ty * 8], a1 = *(float4*)&As[k][ty * 8 + 4];
            float4 b0 = *(float4*)&Bs[k][tx * 8], b1 = *(float4*)&Bs[k][tx * 8 + 4];
            float am[8] = {a0.x, a0.y, a0.z, a0.w, a1.x, a1.y, a1.z, a1.w};
            float bb[8] = {b0.x, b0.y, b0.z, b0.w, b1.x, b1.y, b1.z, b1.w};
#pragma unroll
            for (int i = 0; i < 8; i++)
#pragma unroll
                for (int j = 0; j < 8; j++) acc[i][j] += am[i] * bb[j];
        }
        __syncthreads();
    }
#pragma unroll
    for (int i = 0; i < 8; i++) {
        float* cr = C + (size_t)(bm + ty * 8 + i) * N + bn + tx * 8;
        float4 v0 = {acc[i][0], acc[i][1], acc[i][2], acc[i][3]};
        float4 v1 = {acc[i][4], acc[i][5], acc[i][6], acc[i][7]};
        *(float4*)cr = v0; *(float4*)(cr + 4) = v1;
    }
}

// ---------------- grouped SGEMM (NN), per-expert variable rows -------------
// GATHER_A: A row = x[g_tok[slot]]  (else A row = Abase + slot*Kd)
// SCATTER_C: C row = Cbase + g_dst[slot]*N (else Cbase + slot*N)
template <bool GATHER_A, bool SCATTER_C>
__global__ void __launch_bounds__(256)
sgemm_grouped(const float* __restrict__ Abase, const float* __restrict__ Bbase,
              float* __restrict__ Cbase, int N, int Kd) {
    int e = blockIdx.z;
    int cnt = g_count[e];
    int bm = blockIdx.y * 128;
    if (bm >= cnt) return;
    int bn = blockIdx.x * 128;

    __shared__ float As[8][128];
    __shared__ float Bs[8][128];
    int tid = threadIdx.x;
    int irA = tid >> 1, icA = (tid & 1) * 4;
    int irB = tid >> 5, icB = (tid & 31) * 4;   // NN: 8 k-rows x 128 n
    int tx = tid & 15, ty = tid >> 4;

    const float* B = Bbase + (size_t)e * Kd * N;

    int rA = bm + irA;
    int arow;
    if (rA < cnt) arow = GATHER_A ? g_tok[e * T_TOK + rA] : (e * T_TOK + rA);
    else          arow = GATHER_A ? 0 : e * T_TOK;
    const float* Ap = Abase + (size_t)arow * Kd + icA;
    const float* Bp = B + (size_t)irB * N + bn + icB;

    float acc[8][8];
#pragma unroll
    for (int i = 0; i < 8; i++)
#pragma unroll
        for (int j = 0; j < 8; j++) acc[i][j] = 0.f;

    for (int kk = 0; kk < Kd; kk += 8) {
        float4 av = *(const float4*)(Ap + kk);
        As[icA + 0][irA] = av.x; As[icA + 1][irA] = av.y;
        As[icA + 2][irA] = av.z; As[icA + 3][irA] = av.w;
        float4 bv = *(const float4*)(Bp + (size_t)kk * N);
        *(float4*)&Bs[irB][icB] = bv;
        __syncthreads();
#pragma unroll
        for (int k = 0; k < 8; k++) {
            float4 a0 = *(float4*)&As[k][ty * 8], a1 = *(float4*)&As[k][ty * 8 + 4];
            float4 b0 = *(float4*)&Bs[k][tx * 8], b1 = *(float4*)&Bs[k][tx * 8 + 4];
            float am[8] = {a0.x, a0.y, a0.z, a0.w, a1.x, a1.y, a1.z, a1.w};
            float bb[8] = {b0.x, b0.y, b0.z, b0.w, b1.x, b1.y, b1.z, b1.w};
#pragma unroll
            for (int i = 0; i < 8; i++)
#pragma unroll
                for (int j = 0; j < 8; j++) acc[i][j] += am[i] * bb[j];
        }
        __syncthreads();
    }
#pragma unroll
    for (int i = 0; i < 8; i++) {
        int r = bm + ty * 8 + i;
        if (r >= cnt) continue;
        int crow = SCATTER_C ? g_dst[e * T_TOK + r] : (e * T_TOK + r);
        float* cr = Cbase + (size_t)crow * N + bn + tx * 8;
        float4 v0 = {acc[i][0], acc[i][1], acc[i][2], acc[i][3]};
        float4 v1 = {acc[i][4], acc[i][5], acc[i][6], acc[i][7]};
        *(float4*)cr = v0; *(float4*)(cr + 4) = v1;
    }
}

// ---------------- elementwise ----------------------------------------------
// shared: act = silu(first half) * second half
__global__ void glu_shared_kernel() {
    long long idx = (long long)blockIdx.x * blockDim.x + threadIdx.x;
    if (idx >= (long long)T_TOK * I_DIM) return;
    int t = (int)(idx / I_DIM), c = (int)(idx % I_DIM);
    const float* r = g_sh + (size_t)t * TWO_I;
    float a = r[c], b = r[I_DIM + c];
    g_as[(size_t)t * I_DIM + c] = (a / (1.f + expf(-a))) * b;
}

// experts: act = silu(second half) * first half * routing weight
__global__ void glu_expert_kernel() {
    long long idx = (long long)blockIdx.x * blockDim.x + threadIdx.x;
    if (idx >= (long long)E_NUM * T_TOK * I_DIM) return;
    int c = (int)(idx % I_DIM);
    int slot = (int)(idx / I_DIM);
    int e = slot / T_TOK, pos = slot % T_TOK;
    if (pos >= g_count[e]) return;
    const float* r = g_h1 + (size_t)slot * TWO_I;
    float proj = r[c], gate = r[I_DIM + c];
    float s = gate / (1.f + expf(-gate));
    g_act[(size_t)slot * I_DIM + c] = s * proj * g_w[slot];
}

__global__ void final_add_kernel(float* __restrict__ out) {
    long long idx = (long long)blockIdx.x * blockDim.x + threadIdx.x;
    if (idx >= (long long)T_TOK * H_DIM) return;
    int t = (int)(idx / H_DIM), h = (int)(idx % H_DIM);
    out[idx] += g_par[(size_t)(2 * t) * H_DIM + h] +
                g_par[(size_t)(2 * t + 1) * H_DIM + h];
}

// ---------------- launch -----------------------------------------------------
extern "C" void kernel_launch(void* const* d_in, const int* in_sizes, int n_in,
                              void* d_out, int out_size) {
    const float* x      = (const float*)d_in[0];
    const float* gate_w = (const float*)d_in[1];
    const float* bias   = (const float*)d_in[2];
    const float* Wi     = (const float*)d_in[3];
    const float* Wo     = (const float*)d_in[4];
    const float* sWi    = (const float*)d_in[5];
    const float* sWo    = (const float*)d_in[6];
    float* out = (float*)d_out;

    float *p_h1, *p_act, *p_par, *p_sh, *p_as;
    cudaGetSymbolAddress((void**)&p_h1,  g_h1);
    cudaGetSymbolAddress((void**)&p_act, g_act);
    cudaGetSymbolAddress((void**)&p_par, g_par);
    cudaGetSymbolAddress((void**)&p_sh,  g_sh);
    cudaGetSymbolAddress((void**)&p_as,  g_as);

    zero_counts_kernel<<<1, 32>>>();
    gating_kernel<<<T_TOK / 8, 256>>>(x, gate_w, bias);

    // shared expert up: (4096 x 2304) = x @ sWi^T   (NT)
    sgemm_nt<<<dim3(TWO_I / 128, T_TOK / 128), 256>>>(x, sWi, p_sh, TWO_I, H_DIM);
    glu_shared_kernel<<<((long long)T_TOK * I_DIM + 255) / 256, 256>>>();
    // shared expert down: out = acts @ sWo^T  (NT)  -- writes full output
    sgemm_nt<<<dim3(H_DIM / 128, T_TOK / 128), 256>>>(p_as, sWo, out, H_DIM, I_DIM);

    // expert up: h1[slot] = x[tok[slot]] @ Wi[e]   (NN, gather A)
    sgemm_grouped<true, false><<<dim3(TWO_I / 128, T_TOK / 128, E_NUM), 256>>>(
        x, Wi, p_h1, TWO_I, H_DIM);
    glu_expert_kernel<<<((long long)E_NUM * T_TOK * I_DIM + 255) / 256, 256>>>();
    // expert down: par[dst[slot]] = act[slot] @ Wo[e]  (NN, scatter C)
    sgemm_grouped<false, true><<<dim3(H_DIM / 128, T_TOK / 128, E_NUM), 256>>>(
        p_act, Wo, p_par, H_DIM, I_DIM);

    final_add_kernel<<<((long long)T_TOK * H_DIM + 255) / 256, 256>>>(out);
}

// round 2
// speedup vs baseline: 2.2118x; 2.2118x over previous
#include <cuda_runtime.h>
#include <math.h>
#include <stdint.h>

#define T_TOK 4096
#define H_DIM 768
#define I_DIM 1152
#define TWO_I 2304
#define E_NUM 8
#define SST   132   // smem row stride (uint32) — de-conflicts staging stores

// ---------------- scratch (device globals; no cudaMalloc allowed) ----------
__device__ int   g_count[E_NUM];
__device__ int   g_tok[E_NUM * T_TOK];
__device__ int   g_dst[E_NUM * T_TOK];
__device__ float g_w  [E_NUM * T_TOK];
__device__ float g_h1 [(size_t)E_NUM * T_TOK * TWO_I];
__device__ float g_act[(size_t)E_NUM * T_TOK * I_DIM];
__device__ float g_par[(size_t)T_TOK * 2 * H_DIM];
__device__ float g_sh [(size_t)T_TOK * TWO_I];
__device__ float g_as [(size_t)T_TOK * I_DIM];

// ---------------- tf32 helpers ---------------------------------------------
__device__ __forceinline__ uint32_t f2tf(float f) {
    uint32_t u;
    asm("cvt.rna.tf32.f32 %0, %1;" : "=r"(u) : "f"(f));
    return u;
}

__device__ __forceinline__ void mma8(float* c, const uint32_t* a, const uint32_t* b) {
    asm volatile(
        "mma.sync.aligned.m16n8k8.row.col.f32.tf32.tf32.f32 "
        "{%0,%1,%2,%3},{%4,%5,%6,%7},{%8,%9},{%0,%1,%2,%3};"
        : "+f"(c[0]), "+f"(c[1]), "+f"(c[2]), "+f"(c[3])
        : "r"(a[0]), "r"(a[1]), "r"(a[2]), "r"(a[3]), "r"(b[0]), "r"(b[1]));
}

// ---------------- gating --------------------------------------------------
__global__ void zero_counts_kernel() {
    if (threadIdx.x < E_NUM) g_count[threadIdx.x] = 0;
}

__global__ void gating_kernel(const float* __restrict__ x,
                              const float* __restrict__ gate_w,
                              const float* __restrict__ bias) {
    __shared__ float sgw[E_NUM * H_DIM];
    int tid = threadIdx.x;
    for (int i = tid; i < E_NUM * H_DIM; i += 256) sgw[i] = gate_w[i];
    __syncthreads();

    int warp = tid >> 5, lane = tid & 31;
    int t = blockIdx.x * 8 + warp;
    const float* xr = x + (size_t)t * H_DIM;

    float acc[E_NUM];
#pragma unroll
    for (int e = 0; e < E_NUM; e++) acc[e] = 0.f;
    for (int h = lane; h < H_DIM; h += 32) {
        float xv = xr[h];
#pragma unroll
        for (int e = 0; e < E_NUM; e++) acc[e] += xv * sgw[e * H_DIM + h];
    }
#pragma unroll
    for (int e = 0; e < E_NUM; e++) {
        float v = acc[e];
#pragma unroll
        for (int o = 16; o > 0; o >>= 1) v += __shfl_down_sync(0xffffffffu, v, o);
        acc[e] = v;
    }
    if (lane == 0) {
        float logit[E_NUM];
#pragma unroll
        for (int e = 0; e < E_NUM; e++) logit[e] = 1.f / (1.f + expf(-acc[e]));
        int i0 = 0; float b0 = -1e30f;
#pragma unroll
        for (int e = 0; e < E_NUM; e++) {
            float s = logit[e] + bias[e];
            if (s > b0) { b0 = s; i0 = e; }
        }
        int i1 = 0; float b1 = -1e30f;
#pragma unroll
        for (int e = 0; e < E_NUM; e++) {
            if (e == i0) continue;
            float s = logit[e] + bias[e];
            if (s > b1) { b1 = s; i1 = e; }
        }
        float w0 = logit[i0], w1 = logit[i1];
        float inv = 1.f / (w0 + w1);
        w0 *= inv; w1 *= inv;
        int p0 = atomicAdd(&g_count[i0], 1);
        g_tok[i0 * T_TOK + p0] = t; g_dst[i0 * T_TOK + p0] = 2 * t;     g_w[i0 * T_TOK + p0] = w0;
        int p1 = atomicAdd(&g_count[i1], 1);
        g_tok[i1 * T_TOK + p1] = t; g_dst[i1 * T_TOK + p1] = 2 * t + 1; g_w[i1 * T_TOK + p1] = w1;
    }
}

// ---------------- tf32 MMA GEMM, NT dense ----------------------------------
// C[m][n] = sum_k A[m][k] * B[n][k]; M,N multiples of 128, Kd multiple of 16
__global__ void __launch_bounds__(256)
mm_nt(const float* __restrict__ A, const float* __restrict__ B,
      float* __restrict__ C, int N, int Kd) {
    __shared__ uint32_t As[16][SST];
    __shared__ uint32_t Bs[16][SST];
    int tid = threadIdx.x;
    int bn = blockIdx.x * 128, bm = blockIdx.y * 128;
    int warp = tid >> 5, lane = tid & 31, grp = lane >> 2, qid = lane & 3;
    int wm = warp >> 2, wn = warp & 3;   // warp tile: rows wm*64, cols wn*32

    float acc[4][4][4];
#pragma unroll
    for (int i = 0; i < 4; i++)
#pragma unroll
        for (int j = 0; j < 4; j++)
#pragma unroll
            for (int q = 0; q < 4; q++) acc[i][j][q] = 0.f;

    int lr = tid >> 2, lc = (tid & 3) * 4;
    const float* Ap0 = A + (size_t)(bm + lr) * Kd + lc;
    const float* Ap1 = Ap0 + (size_t)64 * Kd;
    const float* Bp0 = B + (size_t)(bn + lr) * Kd + lc;
    const float* Bp1 = Bp0 + (size_t)64 * Kd;

    for (int kk = 0; kk < Kd; kk += 16) {
        float4 av0 = *(const float4*)(Ap0 + kk);
        float4 av1 = *(const float4*)(Ap1 + kk);
        float4 bv0 = *(const float4*)(Bp0 + kk);
        float4 bv1 = *(const float4*)(Bp1 + kk);
        As[lc + 0][lr] = f2tf(av0.x); As[lc + 1][lr] = f2tf(av0.y);
        As[lc + 2][lr] = f2tf(av0.z); As[lc + 3][lr] = f2tf(av0.w);
        As[lc + 0][lr + 64] = f2tf(av1.x); As[lc + 1][lr + 64] = f2tf(av1.y);
        As[lc + 2][lr + 64] = f2tf(av1.z); As[lc + 3][lr + 64] = f2tf(av1.w);
        Bs[lc + 0][lr] = f2tf(bv0.x); Bs[lc + 1][lr] = f2tf(bv0.y);
        Bs[lc + 2][lr] = f2tf(bv0.z); Bs[lc + 3][lr] = f2tf(bv0.w);
        Bs[lc + 0][lr + 64] = f2tf(bv1.x); Bs[lc + 1][lr + 64] = f2tf(bv1.y);
        Bs[lc + 2][lr + 64] = f2tf(bv1.z); Bs[lc + 3][lr + 64] = f2tf(bv1.w);
        __syncthreads();
#pragma unroll
        for (int ks = 0; ks < 16; ks += 8) {
            uint32_t af[4][4], bf[4][2];
#pragma unroll
            for (int mi = 0; mi < 4; mi++) {
                int m = wm * 64 + mi * 16 + grp;
                af[mi][0] = As[ks + qid][m];
                af[mi][1] = As[ks + qid][m + 8];
                af[mi][2] = As[ks + qid + 4][m];
                af[mi][3] = As[ks + qid + 4][m + 8];
            }
#pragma unroll
            for (int ni = 0; ni < 4; ni++) {
                int n = wn * 32 + ni * 8 + grp;
                bf[ni][0] = Bs[ks + qid][n];
                bf[ni][1] = Bs[ks + qid + 4][n];
            }
#pragma unroll
            for (int mi = 0; mi < 4; mi++)
#pragma unroll
                for (int ni = 0; ni < 4; ni++)
                    mma8(acc[mi][ni], af[mi], bf[ni]);
        }
        __syncthreads();
    }
#pragma unroll
    for (int mi = 0; mi < 4; mi++) {
        int r = bm + wm * 64 + mi * 16 + grp;
#pragma unroll
        for (int ni = 0; ni < 4; ni++) {
            int cx = bn + wn * 32 + ni * 8 + 2 * qid;
            float2 v0 = {acc[mi][ni][0], acc[mi][ni][1]};
            float2 v1 = {acc[mi][ni][2], acc[mi][ni][3]};
            *(float2*)&C[(size_t)r * N + cx] = v0;
            *(float2*)&C[(size_t)(r + 8) * N + cx] = v1;
        }
    }
}

// ---------------- tf32 MMA GEMM, NN grouped per-expert ---------------------
// A rows gathered via g_tok (or linear), C rows scattered via g_dst (or linear)
template <bool GATHER_A, bool SCATTER_C>
__global__ void __launch_bounds__(256)
mm_grouped(const float* __restrict__ Abase, const float* __restrict__ Bbase,
           float* __restrict__ Cbase, int N, int Kd) {
    int e = blockIdx.z;
    int cnt = g_count[e];
    int bm = blockIdx.y * 128;
    if (bm >= cnt) return;
    int bn = blockIdx.x * 128;

    __shared__ uint32_t As[16][SST];
    __shared__ uint32_t Bs[16][SST];
    int tid = threadIdx.x;
    int warp = tid >> 5, lane = tid & 31, grp = lane >> 2, qid = lane & 3;
    int wm = warp >> 2, wn = warp & 3;

    float acc[4][4][4];
#pragma unroll
    for (int i = 0; i < 4; i++)
#pragma unroll
        for (int j = 0; j < 4; j++)
#pragma unroll
            for (int q = 0; q < 4; q++) acc[i][j][q] = 0.f;

    int lr = tid >> 2, lc = (tid & 3) * 4;
    int r0 = bm + lr, r1 = bm + lr + 64;
    int ar0, ar1;
    if (GATHER_A) {
        ar0 = (r0 < cnt) ? g_tok[e * T_TOK + r0] : 0;
        ar1 = (r1 < cnt) ? g_tok[e * T_TOK + r1] : 0;
    } else {
        ar0 = e * T_TOK + ((r0 < cnt) ? r0 : 0);
        ar1 = e * T_TOK + ((r1 < cnt) ? r1 : 0);
    }
    const float* Ap0 = Abase + (size_t)ar0 * Kd + lc;
    const float* Ap1 = Abase + (size_t)ar1 * Kd + lc;

    int br = tid >> 5, bc = (tid & 31) * 4;   // B stage: 8 k-rows x 128 n
    const float* Bp = Bbase + (size_t)e * Kd * N + (size_t)br * N + bn + bc;

    for (int kk = 0; kk < Kd; kk += 16) {
        float4 av0 = *(const float4*)(Ap0 + kk);
        float4 av1 = *(const float4*)(Ap1 + kk);
        float4 bv0 = *(const float4*)(Bp + (size_t)kk * N);
        float4 bv1 = *(const float4*)(Bp + (size_t)(kk + 8) * N);
        As[lc + 0][lr] = f2tf(av0.x); As[lc + 1][lr] = f2tf(av0.y);
        As[lc + 2][lr] = f2tf(av0.z); As[lc + 3][lr] = f2tf(av0.w);
        As[lc + 0][lr + 64] = f2tf(av1.x); As[lc + 1][lr + 64] = f2tf(av1.y);
        As[lc + 2][lr + 64] = f2tf(av1.z); As[lc + 3][lr + 64] = f2tf(av1.w);
        uint4 u0 = {f2tf(bv0.x), f2tf(bv0.y), f2tf(bv0.z), f2tf(bv0.w)};
        uint4 u1 = {f2tf(bv1.x), f2tf(bv1.y), f2tf(bv1.z), f2tf(bv1.w)};
        *(uint4*)&Bs[br][bc]     = u0;
        *(uint4*)&Bs[br + 8][bc] = u1;
        __syncthreads();
#pragma unroll
        for (int ks = 0; ks < 16; ks += 8) {
            uint32_t af[4][4], bf[4][2];
#pragma unroll
            for (int mi = 0; mi < 4; mi++) {
                int m = wm * 64 + mi * 16 + grp;
                af[mi][0] = As[ks + qid][m];
                af[mi][1] = As[ks + qid][m + 8];
                af[mi][2] = As[ks + qid + 4][m];
                af[mi][3] = As[ks + qid + 4][m + 8];
            }
#pragma unroll
            for (int ni = 0; ni < 4; ni++) {
                int n = wn * 32 + ni * 8 + grp;
                bf[ni][0] = Bs[ks + qid][n];
                bf[ni][1] = Bs[ks + qid + 4][n];
            }
#pragma unroll
            for (int mi = 0; mi < 4; mi++)
#pragma unroll
                for (int ni = 0; ni < 4; ni++)
                    mma8(acc[mi][ni], af[mi], bf[ni]);
        }
        __syncthreads();
    }
#pragma unroll
    for (int mi = 0; mi < 4; mi++) {
        int r = bm + wm * 64 + mi * 16 + grp;
        int rA = r, rB = r + 8;
        int cra = -1, crb = -1;
        if (rA < cnt) cra = SCATTER_C ? g_dst[e * T_TOK + rA] : (e * T_TOK + rA);
        if (rB < cnt) crb = SCATTER_C ? g_dst[e * T_TOK + rB] : (e * T_TOK + rB);
#pragma unroll
        for (int ni = 0; ni < 4; ni++) {
            int cx = bn + wn * 32 + ni * 8 + 2 * qid;
            if (cra >= 0) {
                float2 v0 = {acc[mi][ni][0], acc[mi][ni][1]};
                *(float2*)&Cbase[(size_t)cra * N + cx] = v0;
            }
            if (crb >= 0) {
                float2 v1 = {acc[mi][ni][2], acc[mi][ni][3]};
                *(float2*)&Cbase[(size_t)crb * N + cx] = v1;
            }
        }
    }
}

// ---------------- elementwise ----------------------------------------------
__global__ void glu_shared_kernel() {
    long long idx = (long long)blockIdx.x * blockDim.x + threadIdx.x;
    if (idx >= (long long)T_TOK * I_DIM) return;
    int t = (int)(idx / I_DIM), c = (int)(idx % I_DIM);
    const float* r = g_sh + (size_t)t * TWO_I;
    float a = r[c], b = r[I_DIM + c];
    g_as[(size_t)t * I_DIM + c] = (a / (1.f + expf(-a))) * b;
}

__global__ void glu_expert_kernel() {
    long long idx = (long long)blockIdx.x * blockDim.x + threadIdx.x;
    if (idx >= (long long)E_NUM * T_TOK * I_DIM) return;
    int c = (int)(idx % I_DIM);
    int slot = (int)(idx / I_DIM);
    int e = slot / T_TOK, pos = slot % T_TOK;
    if (pos >= g_count[e]) return;
    const float* r = g_h1 + (size_t)slot * TWO_I;
    float proj = r[c], gate = r[I_DIM + c];
    float s = gate / (1.f + expf(-gate));
    g_act[(size_t)slot * I_DIM + c] = s * proj * g_w[slot];
}

__global__ void final_add_kernel(float* __restrict__ out) {
    long long idx = (long long)blockIdx.x * blockDim.x + threadIdx.x;
    if (idx >= (long long)T_TOK * H_DIM) return;
    int t = (int)(idx / H_DIM), h = (int)(idx % H_DIM);
    out[idx] += g_par[(size_t)(2 * t) * H_DIM + h] +
                g_par[(size_t)(2 * t + 1) * H_DIM + h];
}

// ---------------- launch -----------------------------------------------------
extern "C" void kernel_launch(void* const* d_in, const int* in_sizes, int n_in,
                              void* d_out, int out_size) {
    const float* x      = (const float*)d_in[0];
    const float* gate_w = (const float*)d_in[1];
    const float* bias   = (const float*)d_in[2];
    const float* Wi     = (const float*)d_in[3];
    const float* Wo     = (const float*)d_in[4];
    const float* sWi    = (const float*)d_in[5];
    const float* sWo    = (const float*)d_in[6];
    float* out = (float*)d_out;

    float *p_h1, *p_act, *p_par, *p_sh, *p_as;
    cudaGetSymbolAddress((void**)&p_h1,  g_h1);
    cudaGetSymbolAddress((void**)&p_act, g_act);
    cudaGetSymbolAddress((void**)&p_par, g_par);
    cudaGetSymbolAddress((void**)&p_sh,  g_sh);
    cudaGetSymbolAddress((void**)&p_as,  g_as);

    zero_counts_kernel<<<1, 32>>>();
    gating_kernel<<<T_TOK / 8, 256>>>(x, gate_w, bias);

    // shared expert up: (4096 x 2304) = x @ sWi^T   (NT)
    mm_nt<<<dim3(TWO_I / 128, T_TOK / 128), 256>>>(x, sWi, p_sh, TWO_I, H_DIM);
    glu_shared_kernel<<<((long long)T_TOK * I_DIM + 255) / 256, 256>>>();
    // shared expert down: out = acts @ sWo^T  (NT)
    mm_nt<<<dim3(H_DIM / 128, T_TOK / 128), 256>>>(p_as, sWo, out, H_DIM, I_DIM);

    // expert up: h1[slot] = x[tok[slot]] @ Wi[e]   (NN, gather A)
    mm_grouped<true, false><<<dim3(TWO_I / 128, T_TOK / 128, E_NUM), 256>>>(
        x, Wi, p_h1, TWO_I, H_DIM);
    glu_expert_kernel<<<((long long)E_NUM * T_TOK * I_DIM + 255) / 256, 256>>>();
    // expert down: par[dst[slot]] = act[slot] @ Wo[e]  (NN, scatter C)
    mm_grouped<false, true><<<dim3(H_DIM / 128, T_TOK / 128, E_NUM), 256>>>(
        p_act, Wo, p_par, H_DIM, I_DIM);

    final_add_kernel<<<((long long)T_TOK * H_DIM + 255) / 256, 256>>>(out);
}

// round 4
// speedup vs baseline: 2.6296x; 1.1889x over previous
#include <cuda_runtime.h>
#include <math.h>
#include <stdint.h>

#define T_TOK 4096
#define H_DIM 768
#define I_DIM 1152
#define TWO_I 2304
#define E_NUM 8

// ---------------- device-global scratch ------------------------------------
__device__ int   g_count[E_NUM];
__device__ int   g_tok[E_NUM * T_TOK];
__device__ int   g_dst[E_NUM * T_TOK];
__device__ float g_w  [E_NUM * T_TOK];
__device__ float g_h1 [(size_t)E_NUM * T_TOK * TWO_I];   // expert up-proj raw
__device__ float g_act[(size_t)E_NUM * T_TOK * I_DIM];   // expert activated (tf32)
__device__ float g_par[(size_t)T_TOK * 2 * H_DIM];       // per-(t,k) down-proj
__device__ float g_sh [(size_t)T_TOK * TWO_I];           // shared up raw
__device__ float g_as [(size_t)T_TOK * I_DIM];           // shared activated (tf32)
__device__ float g_xt [(size_t)T_TOK * H_DIM];           // x (tf32)
__device__ float g_wi [(size_t)E_NUM * H_DIM * TWO_I];   // Wi (tf32)
__device__ float g_wo [(size_t)E_NUM * I_DIM * H_DIM];   // Wo (tf32)
__device__ float g_swi[(size_t)TWO_I * H_DIM];           // shared_Wi (tf32)
__device__ float g_swo[(size_t)H_DIM * I_DIM];           // shared_Wo (tf32)

// ---------------- helpers ----------------------------------------------------
__device__ __forceinline__ float f2tf_f(float f) {
    uint32_t u;
    asm("cvt.rna.tf32.f32 %0, %1;" : "=r"(u) : "f"(f));
    return __uint_as_float(u);
}

__device__ __forceinline__ void mma8(float* c, const uint32_t* a, const uint32_t* b) {
    asm volatile(
        "mma.sync.aligned.m16n8k8.row.col.f32.tf32.tf32.f32 "
        "{%0,%1,%2,%3},{%4,%5,%6,%7},{%8,%9},{%0,%1,%2,%3};"
        : "+f"(c[0]), "+f"(c[1]), "+f"(c[2]), "+f"(c[3])
        : "r"(a[0]), "r"(a[1]), "r"(a[2]), "r"(a[3]), "r"(b[0]), "r"(b[1]));
}

__device__ __forceinline__ void cpa16(uint32_t dst, const float* src) {
    asm volatile("cp.async.cg.shared.global [%0], [%1], 16;" :: "r"(dst), "l"(src));
}
__device__ __forceinline__ void cpa_commit() {
    asm volatile("cp.async.commit_group;" ::: "memory");
}
template <int NWAIT>
__device__ __forceinline__ void cpa_wait() {
    asm volatile("cp.async.wait_group %0;" :: "n"(NWAIT) : "memory");
}

// ---------------- gating ------------------------------------------------------
__global__ void zero_counts_kernel() {
    if (threadIdx.x < E_NUM) g_count[threadIdx.x] = 0;
}

__global__ void gating_kernel(const float* __restrict__ x,
                              const float* __restrict__ gate_w,
                              const float* __restrict__ bias) {
    __shared__ float sgw[E_NUM * H_DIM];
    int tid = threadIdx.x;
    for (int i = tid; i < E_NUM * H_DIM; i += 256) sgw[i] = gate_w[i];
    __syncthreads();

    int warp = tid >> 5, lane = tid & 31;
    int t = blockIdx.x * 8 + warp;
    const float* xr = x + (size_t)t * H_DIM;

    float acc[E_NUM];
#pragma unroll
    for (int e = 0; e < E_NUM; e++) acc[e] = 0.f;
    for (int h = lane; h < H_DIM; h += 32) {
        float xv = xr[h];
#pragma unroll
        for (int e = 0; e < E_NUM; e++) acc[e] += xv * sgw[e * H_DIM + h];
    }
#pragma unroll
    for (int e = 0; e < E_NUM; e++) {
        float v = acc[e];
#pragma unroll
        for (int o = 16; o > 0; o >>= 1) v += __shfl_down_sync(0xffffffffu, v, o);
        acc[e] = v;
    }
    if (lane == 0) {
        float logit[E_NUM];
#pragma unroll
        for (int e = 0; e < E_NUM; e++) logit[e] = 1.f / (1.f + expf(-acc[e]));
        int i0 = 0; float b0 = -1e30f;
#pragma unroll
        for (int e = 0; e < E_NUM; e++) {
            float s = logit[e] + bias[e];
            if (s > b0) { b0 = s; i0 = e; }
        }
        int i1 = 0; float b1 = -1e30f;
#pragma unroll
        for (int e = 0; e < E_NUM; e++) {
            if (e == i0) continue;
            float s = logit[e] + bias[e];
            if (s > b1) { b1 = s; i1 = e; }
        }
        float w0 = logit[i0], w1 = logit[i1];
        float inv = 1.f / (w0 + w1);
        w0 *= inv; w1 *= inv;
        int p0 = atomicAdd(&g_count[i0], 1);
        g_tok[i0 * T_TOK + p0] = t; g_dst[i0 * T_TOK + p0] = 2 * t;     g_w[i0 * T_TOK + p0] = w0;
        int p1 = atomicAdd(&g_count[i1], 1);
        g_tok[i1 * T_TOK + p1] = t; g_dst[i1 * T_TOK + p1] = 2 * t + 1; g_w[i1 * T_TOK + p1] = w1;
    }
}

// ---------------- prep: tf32 round-copy ---------------------------------------
__global__ void cvt_copy_kernel(const float* __restrict__ src, float* __restrict__ dst,
                                long n4) {
    long i = (long)blockIdx.x * blockDim.x + threadIdx.x;
    if (i >= n4) return;
    float4 v = ((const float4*)src)[i];
    v.x = f2tf_f(v.x); v.y = f2tf_f(v.y); v.z = f2tf_f(v.z); v.w = f2tf_f(v.w);
    ((float4*)dst)[i] = v;
}

// ---------------- pipelined tf32 HMMA GEMM ------------------------------------
// C[m][n] = sum_k A[row(m)][k] * Bmat(n,k); 128x128 tile, BK=16, 4-stage cp.async.
// BLAYOUT 0: B is [K,N] row-major (NN).  BLAYOUT 1: B is [N,K] row-major (NT).
// GRP: per-expert (blockIdx.z), row count from g_count.
// GATHER: A row = g_tok[slot]; SCATTER: C row = g_dst[slot].
#define NSTG 4
#define A_U32 (128 * 20)            // A stage: [m][k] stride 20
#define ASTR  20
#define BSTR_NN 136
#define B_U32_MAX (128 * 20)        // NT stage (NN uses 16*136=2176 < 2560)
#define STG_U32 (A_U32 + B_U32_MAX) // 5120 u32 = 20480 B per stage

template <int N, int K, int BLAYOUT, int GRP, int GATHER, int SCATTER>
__global__ void __launch_bounds__(256, 2)
gemm128(const float* __restrict__ Ab, const float* __restrict__ Bb,
        float* __restrict__ Cb) {
    constexpr int NC = K / 16;
    int e   = GRP ? blockIdx.z : 0;
    int cnt = GRP ? g_count[e] : T_TOK;
    int bm  = blockIdx.y * 128;
    if (bm >= cnt) return;
    int bn  = blockIdx.x * 128;

    extern __shared__ uint32_t sm[];
    uint32_t smaddr = (uint32_t)__cvta_generic_to_shared(sm);
    int tid = threadIdx.x;

    // ---- per-thread staging source pointers
    int am = tid >> 1, ako = (tid & 1) * 8;
    int apos = bm + am;
    long arow;
    if (GATHER)      arow = g_tok[e * T_TOK + ((apos < cnt) ? apos : (cnt - 1))];
    else if (GRP)    arow = (long)e * T_TOK + ((apos < cnt) ? apos : 0);
    else             arow = apos;
    const float* aSrc = Ab + (size_t)arow * K + ako;
    uint32_t aDst = (uint32_t)(am * ASTR + ako) * 4u;

    const float* bSrc;
    uint32_t bDst;
    if (BLAYOUT) {  // NT: B[N][K]
        int nr = tid >> 1, ko = (tid & 1) * 8;
        bSrc = Bb + (size_t)(bn + nr) * K + ko;
        bDst = (uint32_t)(A_U32 + nr * ASTR + ko) * 4u;
    } else {        // NN: B[K][N] (+ expert offset)
        int kr = tid >> 4, n0 = (tid & 15) * 8;
        size_t eoff = GRP ? (size_t)e * K * N : 0;
        bSrc = Bb + eoff + (size_t)kr * N + bn + n0;
        bDst = (uint32_t)(A_U32 + kr * BSTR_NN + n0) * 4u;
    }

    float acc[4][4][4];
#pragma unroll
    for (int i = 0; i < 4; i++)
#pragma unroll
        for (int j = 0; j < 4; j++)
#pragma unroll
            for (int q = 0; q < 4; q++) acc[i][j][q] = 0.f;

    // ---- prologue: stage chunks 0..NSTG-2
#pragma unroll
    for (int s = 0; s < NSTG - 1; s++) {
        uint32_t base = smaddr + (uint32_t)s * STG_U32 * 4u;
        cpa16(base + aDst,      aSrc + s * 16);
        cpa16(base + aDst + 16, aSrc + s * 16 + 4);
        if (BLAYOUT) {
            cpa16(base + bDst,      bSrc + s * 16);
            cpa16(base + bDst + 16, bSrc + s * 16 + 4);
        } else {
            cpa16(base + bDst,      bSrc + (size_t)(s * 16) * N);
            cpa16(base + bDst + 16, bSrc + (size_t)(s * 16) * N + 4);
        }
        cpa_commit();
    }

    int warp = tid >> 5, lane = tid & 31, grp = lane >> 2, qid = lane & 3;
    int wm = warp >> 2, wn = warp & 3;

    // ---- mainloop
    for (int c = 0; c < NC; c++) {
        cpa_wait<NSTG - 2>();
        __syncthreads();

        int pf = c + NSTG - 1;
        if (pf < NC) {
            uint32_t base = smaddr + (uint32_t)(pf & (NSTG - 1)) * STG_U32 * 4u;
            cpa16(base + aDst,      aSrc + pf * 16);
            cpa16(base + aDst + 16, aSrc + pf * 16 + 4);
            if (BLAYOUT) {
                cpa16(base + bDst,      bSrc + pf * 16);
                cpa16(base + bDst + 16, bSrc + pf * 16 + 4);
            } else {
                cpa16(base + bDst,      bSrc + (size_t)(pf * 16) * N);
                cpa16(base + bDst + 16, bSrc + (size_t)(pf * 16) * N + 4);
            }
        }
        cpa_commit();

        const uint32_t* sa = sm + (size_t)(c & (NSTG - 1)) * STG_U32;
        const uint32_t* sb = sa + A_U32;
#pragma unroll
        for (int ks = 0; ks < 16; ks += 8) {
            uint32_t af[4][4], bf[4][2];
#pragma unroll
            for (int mi = 0; mi < 4; mi++) {
                int m = wm * 64 + mi * 16 + grp;
                af[mi][0] = sa[m * ASTR + ks + qid];
                af[mi][1] = sa[(m + 8) * ASTR + ks + qid];
                af[mi][2] = sa[m * ASTR + ks + qid + 4];
                af[mi][3] = sa[(m + 8) * ASTR + ks + qid + 4];
            }
#pragma unroll
            for (int ni = 0; ni < 4; ni++) {
                int n = wn * 32 + ni * 8 + grp;
                if (BLAYOUT) {
                    bf[ni][0] = sb[n * ASTR + ks + qid];
                    bf[ni][1] = sb[n * ASTR + ks + qid + 4];
                } else {
                    bf[ni][0] = sb[(ks + qid) * BSTR_NN + n];
                    bf[ni][1] = sb[(ks + qid + 4) * BSTR_NN + n];
                }
            }
#pragma unroll
            for (int mi = 0; mi < 4; mi++)
#pragma unroll
                for (int ni = 0; ni < 4; ni++)
                    mma8(acc[mi][ni], af[mi], bf[ni]);
        }
    }

    // ---- epilogue
#pragma unroll
    for (int mi = 0; mi < 4; mi++) {
        int r0 = bm + wm * 64 + mi * 16 + grp;
        int r1 = r0 + 8;
        long c0row, c1row;
        if (!GRP) { c0row = r0; c1row = r1; }
        else {
            c0row = (r0 < cnt) ? (SCATTER ? (long)g_dst[e * T_TOK + r0] : (long)e * T_TOK + r0) : -1;
            c1row = (r1 < cnt) ? (SCATTER ? (long)g_dst[e * T_TOK + r1] : (long)e * T_TOK + r1) : -1;
        }
#pragma unroll
        for (int ni = 0; ni < 4; ni++) {
            int cx = bn + wn * 32 + ni * 8 + 2 * qid;
            if (c0row >= 0) {
                float2 v = {acc[mi][ni][0], acc[mi][ni][1]};
                *(float2*)&Cb[(size_t)c0row * N + cx] = v;
            }
            if (c1row >= 0) {
                float2 v = {acc[mi][ni][2], acc[mi][ni][3]};
                *(float2*)&Cb[(size_t)c1row * N + cx] = v;
            }
        }
    }
}

// ---------------- elementwise --------------------------------------------------
__global__ void glu_shared_kernel() {
    long idx = (long)blockIdx.x * blockDim.x + threadIdx.x;
    if (idx >= (long)T_TOK * I_DIM) return;
    int t = (int)(idx / I_DIM), c = (int)(idx % I_DIM);
    const float* r = g_sh + (size_t)t * TWO_I;
    float a = r[c], b = r[I_DIM + c];
    g_as[(size_t)t * I_DIM + c] = f2tf_f((a / (1.f + expf(-a))) * b);
}

__global__ void glu_expert_kernel() {
    long idx = (long)blockIdx.x * blockDim.x + threadIdx.x;
    if (idx >= (long)E_NUM * T_TOK * I_DIM) return;
    int c = (int)(idx % I_DIM);
    int slot = (int)(idx / I_DIM);
    int e = slot / T_TOK, pos = slot % T_TOK;
    if (pos >= g_count[e]) return;
    const float* r = g_h1 + (size_t)slot * TWO_I;
    float proj = r[c], gate = r[I_DIM + c];
    float s = gate / (1.f + expf(-gate));
    g_act[(size_t)slot * I_DIM + c] = f2tf_f(s * proj * g_w[slot]);
}

__global__ void final_add_kernel(float* __restrict__ out) {
    long idx = (long)blockIdx.x * blockDim.x + threadIdx.x;
    if (idx >= (long)T_TOK * H_DIM) return;
    int t = (int)(idx / H_DIM), h = (int)(idx % H_DIM);
    out[idx] += g_par[(size_t)(2 * t) * H_DIM + h] +
                g_par[(size_t)(2 * t + 1) * H_DIM + h];
}

// ---------------- launch --------------------------------------------------------
extern "C" void kernel_launch(void* const* d_in, const int* in_sizes, int n_in,
                              void* d_out, int out_size) {
    const float* x      = (const float*)d_in[0];
    const float* gate_w = (const float*)d_in[1];
    const float* bias   = (const float*)d_in[2];
    const float* Wi     = (const float*)d_in[3];
    const float* Wo     = (const float*)d_in[4];
    const float* sWi    = (const float*)d_in[5];
    const float* sWo    = (const float*)d_in[6];
    float* out = (float*)d_out;

    float *p_h1, *p_act, *p_par, *p_sh, *p_as, *p_xt, *p_wi, *p_wo, *p_swi, *p_swo;
    cudaGetSymbolAddress((void**)&p_h1,  g_h1);
    cudaGetSymbolAddress((void**)&p_act, g_act);
    cudaGetSymbolAddress((void**)&p_par, g_par);
    cudaGetSymbolAddress((void**)&p_sh,  g_sh);
    cudaGetSymbolAddress((void**)&p_as,  g_as);
    cudaGetSymbolAddress((void**)&p_xt,  g_xt);
    cudaGetSymbolAddress((void**)&p_wi,  g_wi);
    cudaGetSymbolAddress((void**)&p_wo,  g_wo);
    cudaGetSymbolAddress((void**)&p_swi, g_swi);
    cudaGetSymbolAddress((void**)&p_swo, g_swo);

    const int SMEM = NSTG * STG_U32 * 4;   // 81920 B

    cudaFuncSetAttribute(gemm128<TWO_I, H_DIM, 1, 0, 0, 0>,
                         cudaFuncAttributeMaxDynamicSharedMemorySize, SMEM);
    cudaFuncSetAttribute(gemm128<TWO_I, H_DIM, 0, 1, 1, 0>,
                         cudaFuncAttributeMaxDynamicSharedMemorySize, SMEM);
    cudaFuncSetAttribute(gemm128<H_DIM, I_DIM, 0, 1, 0, 1>,
                         cudaFuncAttributeMaxDynamicSharedMemorySize, SMEM);
    cudaFuncSetAttribute(gemm128<H_DIM, I_DIM, 1, 0, 0, 0>,
                         cudaFuncAttributeMaxDynamicSharedMemorySize, SMEM);

    zero_counts_kernel<<<1, 32>>>();
    gating_kernel<<<T_TOK / 8, 256>>>(x, gate_w, bias);

    // tf32 round-copies of all GEMM operands
    cvt_copy_kernel<<<((long)T_TOK * H_DIM / 4 + 255) / 256, 256>>>(x, p_xt, (long)T_TOK * H_DIM / 4);
    cvt_copy_kernel<<<((long)E_NUM * H_DIM * TWO_I / 4 + 255) / 256, 256>>>(Wi, p_wi, (long)E_NUM * H_DIM * TWO_I / 4);
    cvt_copy_kernel<<<((long)E_NUM * I_DIM * H_DIM / 4 + 255) / 256, 256>>>(Wo, p_wo, (long)E_NUM * I_DIM * H_DIM / 4);
    cvt_copy_kernel<<<((long)TWO_I * H_DIM / 4 + 255) / 256, 256>>>(sWi, p_swi, (long)TWO_I * H_DIM / 4);
    cvt_copy_kernel<<<((long)H_DIM * I_DIM / 4 + 255) / 256, 256>>>(sWo, p_swo, (long)H_DIM * I_DIM / 4);

    // shared up: g_sh = x @ sWi^T  (NT)
    gemm128<TWO_I, H_DIM, 1, 0, 0, 0><<<dim3(TWO_I / 128, T_TOK / 128), 256, SMEM>>>(p_xt, p_swi, p_sh);
    glu_shared_kernel<<<((long)T_TOK * I_DIM + 255) / 256, 256>>>();

    // expert up: g_h1[slot] = x[g_tok] @ Wi[e]  (NN, gather)
    gemm128<TWO_I, H_DIM, 0, 1, 1, 0><<<dim3(TWO_I / 128, T_TOK / 128, E_NUM), 256, SMEM>>>(p_xt, p_wi, p_h1);
    glu_expert_kernel<<<((long)E_NUM * T_TOK * I_DIM + 255) / 256, 256>>>();

    // expert down: g_par[g_dst] = act @ Wo[e]  (NN, scatter)
    gemm128<H_DIM, I_DIM, 0, 1, 0, 1><<<dim3(H_DIM / 128, T_TOK / 128, E_NUM), 256, SMEM>>>(p_act, p_wo, p_par);

    // shared down: out = as @ sWo^T  (NT)
    gemm128<H_DIM, I_DIM, 1, 0, 0, 0><<<dim3(H_DIM / 128, T_TOK / 128), 256, SMEM>>>(p_as, p_swo, out);

    final_add_kernel<<<((long)T_TOK * H_DIM + 255) / 256, 256>>>(out);
}

// round 5
// speedup vs baseline: 5.9645x; 2.2682x over previous
#include <cuda_runtime.h>
#include <cuda_fp16.h>
#include <math.h>
#include <stdint.h>

#define T_TOK 4096
#define H_DIM 768
#define I_DIM 1152
#define TWO_I 2304
#define E_NUM 8

// ---------------- device-global scratch ------------------------------------
__device__ int    g_count[E_NUM];
__device__ int    g_tok[E_NUM * T_TOK];
__device__ int    g_dst[E_NUM * T_TOK];
__device__ float  g_w  [E_NUM * T_TOK];
__device__ __half g_act[(size_t)E_NUM * T_TOK * I_DIM];  // expert GLU out (fp16)
__device__ __half g_as [(size_t)T_TOK * I_DIM];          // shared GLU out (fp16)
__device__ float  g_par[(size_t)T_TOK * 2 * H_DIM];      // per-(t,k) down-proj
__device__ __half g_hx  [(size_t)T_TOK * H_DIM];         // x fp16
__device__ __half g_hwi [(size_t)E_NUM * H_DIM * TWO_I]; // Wi fp16, cols interleaved
__device__ __half g_hwo [(size_t)E_NUM * I_DIM * H_DIM]; // Wo fp16
__device__ __half g_hswi[(size_t)TWO_I * H_DIM];         // sWi fp16, rows interleaved
__device__ __half g_hswo[(size_t)H_DIM * I_DIM];         // sWo fp16

// ---------------- PTX helpers ------------------------------------------------
__device__ __forceinline__ float silu_f(float v) { return v / (1.f + __expf(-v)); }

__device__ __forceinline__ void mma16(float* c, const uint32_t* a, const uint32_t* b) {
    asm volatile(
        "mma.sync.aligned.m16n8k16.row.col.f32.f16.f16.f32 "
        "{%0,%1,%2,%3},{%4,%5,%6,%7},{%8,%9},{%0,%1,%2,%3};"
        : "+f"(c[0]), "+f"(c[1]), "+f"(c[2]), "+f"(c[3])
        : "r"(a[0]), "r"(a[1]), "r"(a[2]), "r"(a[3]), "r"(b[0]), "r"(b[1]));
}

__device__ __forceinline__ void ldsm4(uint32_t* r, uint32_t a) {
    asm volatile("ldmatrix.sync.aligned.m8n8.x4.shared.b16 {%0,%1,%2,%3}, [%4];"
                 : "=r"(r[0]), "=r"(r[1]), "=r"(r[2]), "=r"(r[3]) : "r"(a));
}
__device__ __forceinline__ void ldsm4t(uint32_t* r, uint32_t a) {
    asm volatile("ldmatrix.sync.aligned.m8n8.x4.trans.shared.b16 {%0,%1,%2,%3}, [%4];"
                 : "=r"(r[0]), "=r"(r[1]), "=r"(r[2]), "=r"(r[3]) : "r"(a));
}

__device__ __forceinline__ void cpa16(uint32_t dst, const void* src) {
    asm volatile("cp.async.cg.shared.global [%0], [%1], 16;" :: "r"(dst), "l"(src));
}
__device__ __forceinline__ void cpa_commit() {
    asm volatile("cp.async.commit_group;" ::: "memory");
}
template <int NWAIT>
__device__ __forceinline__ void cpa_wait() {
    asm volatile("cp.async.wait_group %0;" :: "n"(NWAIT) : "memory");
}

// ---------------- gating ------------------------------------------------------
__global__ void zero_counts_kernel() {
    if (threadIdx.x < E_NUM) g_count[threadIdx.x] = 0;
}

__global__ void gating_kernel(const float* __restrict__ x,
                              const float* __restrict__ gate_w,
                              const float* __restrict__ bias) {
    __shared__ float sgw[E_NUM * H_DIM];
    int tid = threadIdx.x;
    for (int i = tid; i < E_NUM * H_DIM; i += 256) sgw[i] = gate_w[i];
    __syncthreads();

    int warp = tid >> 5, lane = tid & 31;
    int t = blockIdx.x * 8 + warp;
    const float* xr = x + (size_t)t * H_DIM;

    float acc[E_NUM];
#pragma unroll
    for (int e = 0; e < E_NUM; e++) acc[e] = 0.f;
    for (int h = lane; h < H_DIM; h += 32) {
        float xv = xr[h];
#pragma unroll
        for (int e = 0; e < E_NUM; e++) acc[e] += xv * sgw[e * H_DIM + h];
    }
#pragma unroll
    for (int e = 0; e < E_NUM; e++) {
        float v = acc[e];
#pragma unroll
        for (int o = 16; o > 0; o >>= 1) v += __shfl_down_sync(0xffffffffu, v, o);
        acc[e] = v;
    }
    if (lane == 0) {
        float logit[E_NUM];
#pragma unroll
        for (int e = 0; e < E_NUM; e++) logit[e] = 1.f / (1.f + expf(-acc[e]));
        int i0 = 0; float b0 = -1e30f;
#pragma unroll
        for (int e = 0; e < E_NUM; e++) {
            float s = logit[e] + bias[e];
            if (s > b0) { b0 = s; i0 = e; }
        }
        int i1 = 0; float b1 = -1e30f;
#pragma unroll
        for (int e = 0; e < E_NUM; e++) {
            if (e == i0) continue;
            float s = logit[e] + bias[e];
            if (s > b1) { b1 = s; i1 = e; }
        }
        float w0 = logit[i0], w1 = logit[i1];
        float inv = 1.f / (w0 + w1);
        w0 *= inv; w1 *= inv;
        int p0 = atomicAdd(&g_count[i0], 1);
        g_tok[i0 * T_TOK + p0] = t; g_dst[i0 * T_TOK + p0] = 2 * t;     g_w[i0 * T_TOK + p0] = w0;
        int p1 = atomicAdd(&g_count[i1], 1);
        g_tok[i1 * T_TOK + p1] = t; g_dst[i1 * T_TOK + p1] = 2 * t + 1; g_w[i1 * T_TOK + p1] = w1;
    }
}

// ---------------- prep kernels -------------------------------------------------
__global__ void f2h_kernel(const float* __restrict__ src, __half* __restrict__ dst, long n8) {
    long i = (long)blockIdx.x * blockDim.x + threadIdx.x;
    if (i >= n8) return;
    const float4* s = (const float4*)src + i * 2;
    float4 a = s[0], b = s[1];
    __half2 h0 = __floats2half2_rn(a.x, a.y);
    __half2 h1 = __floats2half2_rn(a.z, a.w);
    __half2 h2 = __floats2half2_rn(b.x, b.y);
    __half2 h3 = __floats2half2_rn(b.z, b.w);
    uint4 v = { *(uint32_t*)&h0, *(uint32_t*)&h1, *(uint32_t*)&h2, *(uint32_t*)&h3 };
    ((uint4*)dst)[i] = v;
}

// Wi [E][H][2I] -> interleaved cols: dst[e][k][2j]=src[..][j], [2j+1]=src[..][I+j]
__global__ void ilv_wi_kernel(const float* __restrict__ src, __half* __restrict__ dst) {
    long idx = (long)blockIdx.x * blockDim.x + threadIdx.x;
    if (idx >= (long)E_NUM * H_DIM * I_DIM) return;
    int j = (int)(idx % I_DIM);
    long ek = idx / I_DIM;
    const float* row = src + (size_t)ek * TWO_I;
    __half2 h = __floats2half2_rn(row[j], row[I_DIM + j]);
    ((__half2*)dst)[(size_t)ek * I_DIM + j] = h;
}

// sWi [2I][H] -> interleaved rows: dst[2j]=src[j], dst[2j+1]=src[I+j]
__global__ void ilv_swi_kernel(const float* __restrict__ src, __half* __restrict__ dst) {
    long idx = (long)blockIdx.x * blockDim.x + threadIdx.x;
    if (idx >= (long)TWO_I * (H_DIM / 8)) return;
    int c8 = (int)(idx % (H_DIM / 8));
    int rp = (int)(idx / (H_DIM / 8));
    int srow = (rp >> 1) + (rp & 1) * I_DIM;
    const float4* s = (const float4*)(src + (size_t)srow * H_DIM + c8 * 8);
    float4 a = s[0], b = s[1];
    __half2 h0 = __floats2half2_rn(a.x, a.y);
    __half2 h1 = __floats2half2_rn(a.z, a.w);
    __half2 h2 = __floats2half2_rn(b.x, b.y);
    __half2 h3 = __floats2half2_rn(b.z, b.w);
    uint4 v = { *(uint32_t*)&h0, *(uint32_t*)&h1, *(uint32_t*)&h2, *(uint32_t*)&h3 };
    *(uint4*)(dst + (size_t)rp * H_DIM + c8 * 8) = v;
}

// ---------------- fp16 HMMA GEMM, 128x128 tile, BK=16, 4-stage cp.async --------
// BL 1: B is [N][K] (NT).  BL 0: B is [K][N] (NN).
// EPI 1: shared GLU -> g_as (half). EPI 2: expert GLU*w -> g_act (half).
// EPI 3: fp32 scatter -> g_par.     EPI 4: fp32 + par pair -> out.
#define NSTG  4
#define BOFF  6144u          // A stage = 128 rows * 48B
#define SSB   12544u         // stage stride bytes

template <int N, int K, int BL, int GRP, int GATHER, int EPI>
__global__ void __launch_bounds__(256, 2)
gemm_h(const __half* __restrict__ Ab, const __half* __restrict__ Bb,
       void* __restrict__ Cbv) {
    constexpr int NC = K / 16;
    int e   = GRP ? blockIdx.z : 0;
    int cnt = GRP ? g_count[e] : T_TOK;
    int bm  = blockIdx.y * 128;
    if (bm >= cnt) return;
    int bn  = blockIdx.x * 128;

    extern __shared__ char smc[];
    uint32_t smaddr = (uint32_t)__cvta_generic_to_shared(smc);
    int tid = threadIdx.x;

    // ---- A staging: thread -> (row m, k-octet)
    int am = tid >> 1, aoct = tid & 1;
    int apos = bm + am;
    long arow;
    if (GATHER)   arow = g_tok[e * T_TOK + ((apos < cnt) ? apos : (cnt - 1))];
    else if (GRP) arow = (long)e * T_TOK + ((apos < cnt) ? apos : 0);
    else          arow = apos;
    const __half* aSrc = Ab + (size_t)arow * K + aoct * 8;
    uint32_t aDst = (uint32_t)(am * 48 + aoct * 16);

    // ---- B staging
    const __half* bSrc;
    uint32_t bDst;
    if (BL) {
        int nr = tid >> 1, boct = tid & 1;
        bSrc = Bb + (size_t)(bn + nr) * K + boct * 8;
        bDst = BOFF + (uint32_t)(nr * 48 + boct * 16);
    } else {
        int kr = tid >> 4, n8 = tid & 15;
        size_t eoff = GRP ? (size_t)e * K * N : 0;
        bSrc = Bb + eoff + (size_t)kr * N + bn + n8 * 8;
        bDst = BOFF + (uint32_t)(kr * 272 + n8 * 16);
    }

    float acc[4][4][4];
#pragma unroll
    for (int i = 0; i < 4; i++)
#pragma unroll
        for (int j = 0; j < 4; j++)
#pragma unroll
            for (int q = 0; q < 4; q++) acc[i][j][q] = 0.f;

    // ---- prologue
#pragma unroll
    for (int s = 0; s < NSTG - 1; s++) {
        uint32_t base = smaddr + s * SSB;
        cpa16(base + aDst, aSrc + s * 16);
        if (BL) cpa16(base + bDst, bSrc + s * 16);
        else    cpa16(base + bDst, bSrc + (size_t)s * 16 * N);
        cpa_commit();
    }

    int warp = tid >> 5, lane = tid & 31;
    int wm = warp >> 2, wn = warp & 3;

    // ldmatrix lane-address bases (within a stage)
    uint32_t aLd = (uint32_t)((wm * 64 + (lane & 15)) * 48 + (lane >> 4) * 16);
    uint32_t bLdNT = BOFF + (uint32_t)((wn * 32 + (lane & 7) + (lane >> 4) * 8) * 48 +
                                       ((lane >> 3) & 1) * 16);
    uint32_t bLdNN = BOFF + (uint32_t)((lane & 15) * 272 + (wn * 4 + (lane >> 4)) * 16);

    // ---- mainloop
    for (int c = 0; c < NC; c++) {
        cpa_wait<NSTG - 2>();
        __syncthreads();

        int pf = c + NSTG - 1;
        if (pf < NC) {
            uint32_t base = smaddr + (uint32_t)(pf & 3) * SSB;
            cpa16(base + aDst, aSrc + pf * 16);
            if (BL) cpa16(base + bDst, bSrc + pf * 16);
            else    cpa16(base + bDst, bSrc + (size_t)pf * 16 * N);
        }
        cpa_commit();

        uint32_t sbase = smaddr + (uint32_t)(c & 3) * SSB;
        uint32_t af[4][4], bf[2][4];
#pragma unroll
        for (int mi = 0; mi < 4; mi++) ldsm4(af[mi], sbase + aLd + mi * (16 * 48));
        if (BL) {
#pragma unroll
            for (int p = 0; p < 2; p++) ldsm4(bf[p], sbase + bLdNT + p * (16 * 48));
        } else {
#pragma unroll
            for (int p = 0; p < 2; p++) ldsm4t(bf[p], sbase + bLdNN + p * 32);
        }
#pragma unroll
        for (int mi = 0; mi < 4; mi++)
#pragma unroll
            for (int ni = 0; ni < 4; ni++) {
                uint32_t b2[2] = { bf[ni >> 1][(ni & 1) * 2], bf[ni >> 1][(ni & 1) * 2 + 1] };
                mma16(acc[mi][ni], af[mi], b2);
            }
    }

    // ---- epilogue
    int g = lane >> 2, q = lane & 3;

    if (EPI == 1 || EPI == 2) {
        __half* C = (__half*)Cbv;
#pragma unroll
        for (int mi = 0; mi < 4; mi++) {
            int r0 = bm + wm * 64 + mi * 16 + g;
            int r1 = r0 + 8;
            long o0 = -1, o1 = -1;
            float w0 = 1.f, w1 = 1.f;
            if (EPI == 1) { o0 = r0; o1 = r1; }
            else {
                if (r0 < cnt) { o0 = (long)e * T_TOK + r0; w0 = g_w[e * T_TOK + r0]; }
                if (r1 < cnt) { o1 = (long)e * T_TOK + r1; w1 = g_w[e * T_TOK + r1]; }
            }
#pragma unroll
            for (int ni = 0; ni < 4; ni++) {
                int col = (bn >> 1) + wn * 16 + ni * 4 + q;
                float d0 = acc[mi][ni][0], d1 = acc[mi][ni][1];
                float d2 = acc[mi][ni][2], d3 = acc[mi][ni][3];
                if (o0 >= 0) {
                    float v = (EPI == 1) ? silu_f(d0) * d1 : silu_f(d1) * d0 * w0;
                    C[o0 * I_DIM + col] = __float2half(v);
                }
                if (o1 >= 0) {
                    float v = (EPI == 1) ? silu_f(d2) * d3 : silu_f(d3) * d2 * w1;
                    C[o1 * I_DIM + col] = __float2half(v);
                }
            }
        }
    } else if (EPI == 3) {
        float* C = (float*)Cbv;
#pragma unroll
        for (int mi = 0; mi < 4; mi++) {
            int r0 = bm + wm * 64 + mi * 16 + g;
            int r1 = r0 + 8;
            long o0 = (r0 < cnt) ? (long)g_dst[e * T_TOK + r0] : -1;
            long o1 = (r1 < cnt) ? (long)g_dst[e * T_TOK + r1] : -1;
#pragma unroll
            for (int ni = 0; ni < 4; ni++) {
                int cx = bn + wn * 32 + ni * 8 + 2 * q;
                if (o0 >= 0) {
                    float2 v = { acc[mi][ni][0], acc[mi][ni][1] };
                    *(float2*)&C[o0 * H_DIM + cx] = v;
                }
                if (o1 >= 0) {
                    float2 v = { acc[mi][ni][2], acc[mi][ni][3] };
                    *(float2*)&C[o1 * H_DIM + cx] = v;
                }
            }
        }
    } else {  // EPI 4: out = acc + par[2t] + par[2t+1]
        float* C = (float*)Cbv;
#pragma unroll
        for (int mi = 0; mi < 4; mi++) {
            int r0 = bm + wm * 64 + mi * 16 + g;
            int r1 = r0 + 8;
#pragma unroll
            for (int ni = 0; ni < 4; ni++) {
                int cx = bn + wn * 32 + ni * 8 + 2 * q;
                {
                    float2 p0 = *(float2*)&g_par[(size_t)(2 * r0) * H_DIM + cx];
                    float2 p1 = *(float2*)&g_par[(size_t)(2 * r0 + 1) * H_DIM + cx];
                    float2 v = { acc[mi][ni][0] + p0.x + p1.x,
                                 acc[mi][ni][1] + p0.y + p1.y };
                    *(float2*)&C[(size_t)r0 * H_DIM + cx] = v;
                }
                {
                    float2 p0 = *(float2*)&g_par[(size_t)(2 * r1) * H_DIM + cx];
                    float2 p1 = *(float2*)&g_par[(size_t)(2 * r1 + 1) * H_DIM + cx];
                    float2 v = { acc[mi][ni][2] + p0.x + p1.x,
                                 acc[mi][ni][3] + p0.y + p1.y };
                    *(float2*)&C[(size_t)r1 * H_DIM + cx] = v;
                }
            }
        }
    }
}

// ---------------- launch ---------------------------------------------------------
extern "C" void kernel_launch(void* const* d_in, const int* in_sizes, int n_in,
                              void* d_out, int out_size) {
    const float* x      = (const float*)d_in[0];
    const float* gate_w = (const float*)d_in[1];
    const float* bias   = (const float*)d_in[2];
    const float* Wi     = (const float*)d_in[3];
    const float* Wo     = (const float*)d_in[4];
    const float* sWi    = (const float*)d_in[5];
    const float* sWo    = (const float*)d_in[6];
    float* out = (float*)d_out;

    __half *p_act, *p_as, *p_hx, *p_hwi, *p_hwo, *p_hswi, *p_hswo;
    float* p_par;
    cudaGetSymbolAddress((void**)&p_act,  g_act);
    cudaGetSymbolAddress((void**)&p_as,   g_as);
    cudaGetSymbolAddress((void**)&p_par,  g_par);
    cudaGetSymbolAddress((void**)&p_hx,   g_hx);
    cudaGetSymbolAddress((void**)&p_hwi,  g_hwi);
    cudaGetSymbolAddress((void**)&p_hwo,  g_hwo);
    cudaGetSymbolAddress((void**)&p_hswi, g_hswi);
    cudaGetSymbolAddress((void**)&p_hswo, g_hswo);

    const int SMEM = NSTG * SSB;   // 50176 B

    cudaFuncSetAttribute(gemm_h<TWO_I, H_DIM, 1, 0, 0, 1>,
                         cudaFuncAttributeMaxDynamicSharedMemorySize, SMEM);
    cudaFuncSetAttribute(gemm_h<TWO_I, H_DIM, 0, 1, 1, 2>,
                         cudaFuncAttributeMaxDynamicSharedMemorySize, SMEM);
    cudaFuncSetAttribute(gemm_h<H_DIM, I_DIM, 0, 1, 0, 3>,
                         cudaFuncAttributeMaxDynamicSharedMemorySize, SMEM);
    cudaFuncSetAttribute(gemm_h<H_DIM, I_DIM, 1, 0, 0, 4>,
                         cudaFuncAttributeMaxDynamicSharedMemorySize, SMEM);

    zero_counts_kernel<<<1, 32>>>();
    gating_kernel<<<T_TOK / 8, 256>>>(x, gate_w, bias);

    // fp16 prep
    f2h_kernel<<<((long)T_TOK * H_DIM / 8 + 255) / 256, 256>>>(x, p_hx, (long)T_TOK * H_DIM / 8);
    ilv_wi_kernel<<<((long)E_NUM * H_DIM * I_DIM + 255) / 256, 256>>>(Wi, p_hwi);
    f2h_kernel<<<((long)E_NUM * I_DIM * H_DIM / 8 + 255) / 256, 256>>>(Wo, p_hwo,
                                                                       (long)E_NUM * I_DIM * H_DIM / 8);
    ilv_swi_kernel<<<((long)TWO_I * (H_DIM / 8) + 255) / 256, 256>>>(sWi, p_hswi);
    f2h_kernel<<<((long)H_DIM * I_DIM / 8 + 255) / 256, 256>>>(sWo, p_hswo, (long)H_DIM * I_DIM / 8);

    // shared up + GLU -> g_as  (NT, interleaved rows)
    gemm_h<TWO_I, H_DIM, 1, 0, 0, 1><<<dim3(TWO_I / 128, T_TOK / 128), 256, SMEM>>>(
        p_hx, p_hswi, p_as);
    // expert up + GLU*w -> g_act  (NN, gather, interleaved cols)
    gemm_h<TWO_I, H_DIM, 0, 1, 1, 2><<<dim3(TWO_I / 128, T_TOK / 128, E_NUM), 256, SMEM>>>(
        p_hx, p_hwi, p_act);
    // expert down -> g_par (NN, scatter)
    gemm_h<H_DIM, I_DIM, 0, 1, 0, 3><<<dim3(H_DIM / 128, T_TOK / 128, E_NUM), 256, SMEM>>>(
        p_act, p_hwo, p_par);
    // shared down + final add -> out (NT)
    gemm_h<H_DIM, I_DIM, 1, 0, 0, 4><<<dim3(H_DIM / 128, T_TOK / 128), 256, SMEM>>>(
        p_as, p_hswo, out);
}

// round 6
// speedup vs baseline: 6.7240x; 1.1273x over previous
#include <cuda_runtime.h>
#include <cuda_fp16.h>
#include <math.h>
#include <stdint.h>

#define T_TOK 4096
#define H_DIM 768
#define I_DIM 1152
#define TWO_I 2304
#define E_NUM 8

// ---------------- device-global scratch ------------------------------------
__device__ int    g_count[E_NUM];
__device__ int    g_tok[E_NUM * T_TOK];
__device__ int    g_dst[E_NUM * T_TOK];
__device__ float  g_w  [E_NUM * T_TOK];
__device__ __half g_act[(size_t)E_NUM * T_TOK * I_DIM];  // expert GLU out
__device__ __half g_as [(size_t)T_TOK * I_DIM];          // shared GLU out
__device__ float  g_par[(size_t)T_TOK * 2 * H_DIM];      // per-(t,k) down-proj
__device__ __half g_hx  [(size_t)T_TOK * H_DIM];         // x fp16
__device__ __half g_hwi [(size_t)E_NUM * H_DIM * TWO_I]; // Wi fp16 (plain)
__device__ __half g_hwo [(size_t)E_NUM * I_DIM * H_DIM]; // Wo fp16 (plain)
__device__ __half g_hswi[(size_t)TWO_I * H_DIM];         // sWi fp16 (plain)
__device__ __half g_hswo[(size_t)H_DIM * I_DIM];         // sWo fp16 (plain)

// ---------------- PTX helpers ------------------------------------------------
__device__ __forceinline__ float silu_f(float v) { return v / (1.f + __expf(-v)); }

__device__ __forceinline__ void mma16(float* c, const uint32_t* a, const uint32_t* b) {
    asm volatile(
        "mma.sync.aligned.m16n8k16.row.col.f32.f16.f16.f32 "
        "{%0,%1,%2,%3},{%4,%5,%6,%7},{%8,%9},{%0,%1,%2,%3};"
        : "+f"(c[0]), "+f"(c[1]), "+f"(c[2]), "+f"(c[3])
        : "r"(a[0]), "r"(a[1]), "r"(a[2]), "r"(a[3]), "r"(b[0]), "r"(b[1]));
}
__device__ __forceinline__ void ldsm4(uint32_t* r, uint32_t a) {
    asm volatile("ldmatrix.sync.aligned.m8n8.x4.shared.b16 {%0,%1,%2,%3}, [%4];"
                 : "=r"(r[0]), "=r"(r[1]), "=r"(r[2]), "=r"(r[3]) : "r"(a));
}
__device__ __forceinline__ void ldsm4t(uint32_t* r, uint32_t a) {
    asm volatile("ldmatrix.sync.aligned.m8n8.x4.trans.shared.b16 {%0,%1,%2,%3}, [%4];"
                 : "=r"(r[0]), "=r"(r[1]), "=r"(r[2]), "=r"(r[3]) : "r"(a));
}
__device__ __forceinline__ void cpa16(uint32_t dst, const void* src) {
    asm volatile("cp.async.cg.shared.global [%0], [%1], 16;" :: "r"(dst), "l"(src));
}
__device__ __forceinline__ void cpa_commit() {
    asm volatile("cp.async.commit_group;" ::: "memory");
}
template <int NWAIT>
__device__ __forceinline__ void cpa_wait() {
    asm volatile("cp.async.wait_group %0;" :: "n"(NWAIT) : "memory");
}

// ---------------- gating ------------------------------------------------------
__global__ void zero_counts_kernel() {
    if (threadIdx.x < E_NUM) g_count[threadIdx.x] = 0;
}

__global__ void gating_kernel(const float* __restrict__ x,
                              const float* __restrict__ gate_w,
                              const float* __restrict__ bias) {
    __shared__ float sgw[E_NUM * H_DIM];
    int tid = threadIdx.x;
    for (int i = tid; i < E_NUM * H_DIM; i += 256) sgw[i] = gate_w[i];
    __syncthreads();

    int warp = tid >> 5, lane = tid & 31;
    int t = blockIdx.x * 8 + warp;
    const float* xr = x + (size_t)t * H_DIM;

    float acc[E_NUM];
#pragma unroll
    for (int e = 0; e < E_NUM; e++) acc[e] = 0.f;
    for (int h = lane; h < H_DIM; h += 32) {
        float xv = xr[h];
#pragma unroll
        for (int e = 0; e < E_NUM; e++) acc[e] += xv * sgw[e * H_DIM + h];
    }
#pragma unroll
    for (int e = 0; e < E_NUM; e++) {
        float v = acc[e];
#pragma unroll
        for (int o = 16; o > 0; o >>= 1) v += __shfl_down_sync(0xffffffffu, v, o);
        acc[e] = v;
    }
    if (lane == 0) {
        float logit[E_NUM];
#pragma unroll
        for (int e = 0; e < E_NUM; e++) logit[e] = 1.f / (1.f + expf(-acc[e]));
        int i0 = 0; float b0 = -1e30f;
#pragma unroll
        for (int e = 0; e < E_NUM; e++) {
            float s = logit[e] + bias[e];
            if (s > b0) { b0 = s; i0 = e; }
        }
        int i1 = 0; float b1 = -1e30f;
#pragma unroll
        for (int e = 0; e < E_NUM; e++) {
            if (e == i0) continue;
            float s = logit[e] + bias[e];
            if (s > b1) { b1 = s; i1 = e; }
        }
        float w0 = logit[i0], w1 = logit[i1];
        float inv = 1.f / (w0 + w1);
        w0 *= inv; w1 *= inv;
        int p0 = atomicAdd(&g_count[i0], 1);
        g_tok[i0 * T_TOK + p0] = t; g_dst[i0 * T_TOK + p0] = 2 * t;     g_w[i0 * T_TOK + p0] = w0;
        int p1 = atomicAdd(&g_count[i1], 1);
        g_tok[i1 * T_TOK + p1] = t; g_dst[i1 * T_TOK + p1] = 2 * t + 1; g_w[i1 * T_TOK + p1] = w1;
    }
}

// ---------------- merged f32->f16 conversion (all 5 tensors, one launch) -------
#define N8_X   ((long)T_TOK * H_DIM / 8)
#define N8_WI  ((long)E_NUM * H_DIM * TWO_I / 8)
#define N8_WO  ((long)E_NUM * I_DIM * H_DIM / 8)
#define N8_SWI ((long)TWO_I * H_DIM / 8)
#define N8_SWO ((long)H_DIM * I_DIM / 8)
#define N8_TOT (N8_X + N8_WI + N8_WO + N8_SWI + N8_SWO)

__global__ void f2h_all_kernel(const float* __restrict__ x,  const float* __restrict__ wi,
                               const float* __restrict__ wo, const float* __restrict__ swi,
                               const float* __restrict__ swo) {
    long i = (long)blockIdx.x * blockDim.x + threadIdx.x;
    if (i >= N8_TOT) return;
    const float* src; __half* dst; long off;
    if (i < N8_X)                          { src = x;   dst = g_hx;   off = i; }
    else if (i < N8_X + N8_WI)             { src = wi;  dst = g_hwi;  off = i - N8_X; }
    else if (i < N8_X + N8_WI + N8_WO)     { src = wo;  dst = g_hwo;  off = i - N8_X - N8_WI; }
    else if (i < N8_TOT - N8_SWO)          { src = swi; dst = g_hswi; off = i - N8_X - N8_WI - N8_WO; }
    else                                   { src = swo; dst = g_hswo; off = i - (N8_TOT - N8_SWO); }
    const float4* s = (const float4*)src + off * 2;
    float4 a = s[0], b = s[1];
    __half2 h0 = __floats2half2_rn(a.x, a.y);
    __half2 h1 = __floats2half2_rn(a.z, a.w);
    __half2 h2 = __floats2half2_rn(b.x, b.y);
    __half2 h3 = __floats2half2_rn(b.z, b.w);
    uint4 v = { *(uint32_t*)&h0, *(uint32_t*)&h1, *(uint32_t*)&h2, *(uint32_t*)&h3 };
    ((uint4*)dst)[off] = v;
}

// ================= UP GEMM: 128 rows x 128 GLU cols, split-B, BK=32 ============
// BL 1 (NT): B is [2I][K] (shared sWi). BL 0 (NN): B is [K][2I] (expert Wi).
// EPI 1: g_as = silu(proj)*gate. EPI 2: g_act = silu(gate)*proj*w.
// 512 threads, 3-stage cp.async, A stride 80B, NN B stride 272B.
#define U_ASTR 80u
#define U_ATILE 10240u
#define U_BT_NT 10240u
#define U_BT_NN 8704u

template <int BL, int EPI>
__global__ void __launch_bounds__(512, 1)
up_gemm(const __half* __restrict__ Ab, const __half* __restrict__ Bb,
        __half* __restrict__ C) {
    constexpr int K = H_DIM, NC = K / 32;
    constexpr uint32_t BT = BL ? U_BT_NT : U_BT_NN;
    constexpr uint32_t SSB = U_ATILE + 2 * BT;
    constexpr int GRP = (EPI == 2);

    int e   = GRP ? blockIdx.z : 0;
    int cnt = GRP ? g_count[e] : T_TOK;
    int bm  = blockIdx.y * 128;
    if (bm >= cnt) return;
    int c0  = blockIdx.x * 128;

    extern __shared__ char smc[];
    uint32_t smaddr = (uint32_t)__cvta_generic_to_shared(smc);
    int tid = threadIdx.x;

    // ---- A staging: row = tid>>2, seg = tid&3 (16B)
    int am = tid >> 2, aseg = tid & 3;
    int apos = bm + am;
    long arow;
    if (GRP) arow = g_tok[e * T_TOK + ((apos < cnt) ? apos : (cnt - 1))];
    else     arow = apos;
    const __half* aSrc = Ab + (size_t)arow * K + aseg * 8;
    uint32_t aDst = (uint32_t)am * U_ASTR + aseg * 16;

    // ---- B staging
    const __half *bSrc0, *bSrc1;
    uint32_t bDst0, bDst1;
    if (BL) {   // NT: rows c0+nr and I+c0+nr of [2I][K]
        int nr = tid >> 2, seg = tid & 3;
        bSrc0 = Bb + (size_t)(c0 + nr) * K + seg * 8;
        bSrc1 = Bb + (size_t)(I_DIM + c0 + nr) * K + seg * 8;
        bDst0 = U_ATILE + (uint32_t)nr * U_ASTR + seg * 16;
        bDst1 = bDst0 + U_BT_NT;
    } else {    // NN: [K][2I], cols c0.. and I+c0..
        int kr = tid >> 4, n8 = tid & 15;
        size_t eoff = (size_t)e * K * TWO_I;
        bSrc0 = Bb + eoff + (size_t)kr * TWO_I + c0 + n8 * 8;
        bSrc1 = bSrc0 + I_DIM;
        bDst0 = U_ATILE + (uint32_t)kr * 272 + n8 * 16;
        bDst1 = bDst0 + U_BT_NN;
    }

    float acc[2][8][4];
#pragma unroll
    for (int i = 0; i < 2; i++)
#pragma unroll
        for (int j = 0; j < 8; j++)
#pragma unroll
            for (int q = 0; q < 4; q++) acc[i][j][q] = 0.f;

    // ---- prologue: 2 stages
#pragma unroll
    for (int s = 0; s < 2; s++) {
        uint32_t base = smaddr + s * SSB;
        cpa16(base + aDst, aSrc + s * 32);
        if (BL) {
            cpa16(base + bDst0, bSrc0 + s * 32);
            cpa16(base + bDst1, bSrc1 + s * 32);
        } else {
            cpa16(base + bDst0, bSrc0 + (size_t)s * 32 * TWO_I);
            cpa16(base + bDst1, bSrc1 + (size_t)s * 32 * TWO_I);
        }
        cpa_commit();
    }

    int warp = tid >> 5, lane = tid & 31;
    int wm = warp >> 2, wn = warp & 3;

    uint32_t aLd = (uint32_t)(wm * 32 + (lane & 15)) * U_ASTR + (lane >> 4) * 16;
    uint32_t bLdNT = U_ATILE + (uint32_t)(wn * 32 + (lane & 7) + ((lane >> 4) * 8)) * U_ASTR +
                     ((lane >> 3) & 1) * 16;
    uint32_t bLdNN = U_ATILE + (uint32_t)(lane & 15) * 272 + (wn * 4 + (lane >> 4)) * 16;

    // ---- mainloop
    for (int c = 0; c < NC; c++) {
        cpa_wait<1>();
        __syncthreads();

        int pf = c + 2;
        if (pf < NC) {
            uint32_t base = smaddr + (uint32_t)(pf % 3) * SSB;
            cpa16(base + aDst, aSrc + pf * 32);
            if (BL) {
                cpa16(base + bDst0, bSrc0 + pf * 32);
                cpa16(base + bDst1, bSrc1 + pf * 32);
            } else {
                cpa16(base + bDst0, bSrc0 + (size_t)pf * 32 * TWO_I);
                cpa16(base + bDst1, bSrc1 + (size_t)pf * 32 * TWO_I);
            }
        }
        cpa_commit();

        uint32_t sbase = smaddr + (uint32_t)(c % 3) * SSB;
#pragma unroll
        for (int ks = 0; ks < 2; ks++) {
            uint32_t af[2][4], bf[2][2][4];
#pragma unroll
            for (int mi = 0; mi < 2; mi++)
                ldsm4(af[mi], sbase + aLd + mi * (16 * U_ASTR) + ks * 32);
#pragma unroll
            for (int t = 0; t < 2; t++)
#pragma unroll
                for (int p = 0; p < 2; p++) {
                    if (BL)
                        ldsm4(bf[t][p], sbase + bLdNT + t * U_BT_NT +
                                        p * (16 * U_ASTR) + ks * 32);
                    else
                        ldsm4t(bf[t][p], sbase + bLdNN + t * U_BT_NN +
                                         (uint32_t)ks * (16 * 272) + p * 32);
                }
#pragma unroll
            for (int mi = 0; mi < 2; mi++)
#pragma unroll
                for (int t = 0; t < 2; t++)
#pragma unroll
                    for (int p = 0; p < 2; p++)
#pragma unroll
                        for (int j = 0; j < 2; j++) {
                            uint32_t b2[2] = { bf[t][p][j * 2], bf[t][p][j * 2 + 1] };
                            mma16(acc[mi][t * 4 + p * 2 + j], af[mi], b2);
                        }
        }
    }

    // ---- epilogue: GLU across tiles, half2 stores
    int g = lane >> 2, q = lane & 3;
#pragma unroll
    for (int mi = 0; mi < 2; mi++) {
        int r0 = bm + wm * 32 + mi * 16 + g;
        int r1 = r0 + 8;
        long o0 = -1, o1 = -1;
        float w0 = 1.f, w1 = 1.f;
        if (EPI == 1) { o0 = r0; o1 = r1; }
        else {
            if (r0 < cnt) { o0 = (long)e * T_TOK + r0; w0 = g_w[e * T_TOK + r0]; }
            if (r1 < cnt) { o1 = (long)e * T_TOK + r1; w1 = g_w[e * T_TOK + r1]; }
        }
#pragma unroll
        for (int nidx = 0; nidx < 4; nidx++) {
            int col = c0 + wn * 32 + (nidx >> 1) * 16 + (nidx & 1) * 8 + 2 * q;
            float p0 = acc[mi][nidx][0],     p1 = acc[mi][nidx][1];
            float p2 = acc[mi][nidx][2],     p3 = acc[mi][nidx][3];
            float g0 = acc[mi][4 + nidx][0], g1 = acc[mi][4 + nidx][1];
            float g2 = acc[mi][4 + nidx][2], g3 = acc[mi][4 + nidx][3];
            if (o0 >= 0) {
                float v0 = (EPI == 1) ? silu_f(p0) * g0 : silu_f(g0) * p0 * w0;
                float v1 = (EPI == 1) ? silu_f(p1) * g1 : silu_f(g1) * p1 * w0;
                *(__half2*)&C[o0 * I_DIM + col] = __floats2half2_rn(v0, v1);
            }
            if (o1 >= 0) {
                float v0 = (EPI == 1) ? silu_f(p2) * g2 : silu_f(g2) * p2 * w1;
                float v1 = (EPI == 1) ? silu_f(p3) * g3 : silu_f(g3) * p3 * w1;
                *(__half2*)&C[o1 * I_DIM + col] = __floats2half2_rn(v0, v1);
            }
        }
    }
}

// ================= DOWN GEMM: 128x128, BK=32, 256 threads ======================
// BL 0 (NN): B=[K][N] expert Wo, scatter rows to g_par (EPI 3).
// BL 1 (NT): B=[N][K] shared sWo, out = acc + par pair (EPI 4).
#define D_ASTR 80u
#define D_ATILE 10240u
#define D_BT_NT 10240u
#define D_BT_NN 8704u

template <int BL, int EPI>
__global__ void __launch_bounds__(256, 2)
down_gemm(const __half* __restrict__ Ab, const __half* __restrict__ Bb,
          float* __restrict__ C) {
    constexpr int N = H_DIM, K = I_DIM, NC = K / 32;
    constexpr uint32_t BT = BL ? D_BT_NT : D_BT_NN;
    constexpr uint32_t SSB = D_ATILE + BT;
    constexpr int GRP = (EPI == 3);

    int e   = GRP ? blockIdx.z : 0;
    int cnt = GRP ? g_count[e] : T_TOK;
    int bm  = blockIdx.y * 128;
    if (bm >= cnt) return;
    int bn  = blockIdx.x * 128;

    extern __shared__ char smc[];
    uint32_t smaddr = (uint32_t)__cvta_generic_to_shared(smc);
    int tid = threadIdx.x;

    // ---- A staging: row = tid>>1, 2 segs
    int am = tid >> 1, as0 = (tid & 1) * 2;
    int apos = bm + am;
    long arow = GRP ? ((long)e * T_TOK + ((apos < cnt) ? apos : 0)) : apos;
    const __half* aSrc = Ab + (size_t)arow * K + as0 * 8;
    uint32_t aDst = (uint32_t)am * D_ASTR + as0 * 16;

    // ---- B staging
    const __half* bSrc;
    uint32_t bDst;
    int bseg0 = 0;
    if (BL) {
        int nr = tid >> 1;
        bSrc = Bb + (size_t)(bn + nr) * K + as0 * 8;
        bDst = D_ATILE + (uint32_t)nr * D_ASTR + as0 * 16;
    } else {
        int kr = tid >> 3; bseg0 = tid & 7;
        size_t eoff = (size_t)e * K * N;
        bSrc = Bb + eoff + (size_t)kr * N + bn + bseg0 * 8;
        bDst = D_ATILE + (uint32_t)kr * 272 + bseg0 * 16;
    }

    float acc[4][4][4];
#pragma unroll
    for (int i = 0; i < 4; i++)
#pragma unroll
        for (int j = 0; j < 4; j++)
#pragma unroll
            for (int q = 0; q < 4; q++) acc[i][j][q] = 0.f;

#pragma unroll
    for (int s = 0; s < 2; s++) {
        uint32_t base = smaddr + s * SSB;
        cpa16(base + aDst,      aSrc + s * 32);
        cpa16(base + aDst + 16, aSrc + s * 32 + 8);
        if (BL) {
            cpa16(base + bDst,      bSrc + s * 32);
            cpa16(base + bDst + 16, bSrc + s * 32 + 8);
        } else {
            cpa16(base + bDst,       bSrc + (size_t)s * 32 * N);
            cpa16(base + bDst + 128, bSrc + (size_t)s * 32 * N + 64);
        }
        cpa_commit();
    }

    int warp = tid >> 5, lane = tid & 31;
    int wm = warp >> 2, wn = warp & 3;

    uint32_t aLd = (uint32_t)(wm * 64 + (lane & 15)) * D_ASTR + (lane >> 4) * 16;
    uint32_t bLdNT = D_ATILE + (uint32_t)(wn * 32 + (lane & 7) + ((lane >> 4) * 8)) * D_ASTR +
                     ((lane >> 3) & 1) * 16;
    uint32_t bLdNN = D_ATILE + (uint32_t)(lane & 15) * 272 + (wn * 4 + (lane >> 4)) * 16;

    for (int c = 0; c < NC; c++) {
        cpa_wait<1>();
        __syncthreads();

        int pf = c + 2;
        if (pf < NC) {
            uint32_t base = smaddr + (uint32_t)(pf % 3) * SSB;
            cpa16(base + aDst,      aSrc + pf * 32);
            cpa16(base + aDst + 16, aSrc + pf * 32 + 8);
            if (BL) {
                cpa16(base + bDst,      bSrc + pf * 32);
                cpa16(base + bDst + 16, bSrc + pf * 32 + 8);
            } else {
                cpa16(base + bDst,       bSrc + (size_t)pf * 32 * N);
                cpa16(base + bDst + 128, bSrc + (size_t)pf * 32 * N + 64);
            }
        }
        cpa_commit();

        uint32_t sbase = smaddr + (uint32_t)(c % 3) * SSB;
#pragma unroll
        for (int ks = 0; ks < 2; ks++) {
            uint32_t af[4][4], bf[2][4];
#pragma unroll
            for (int mi = 0; mi < 4; mi++)
                ldsm4(af[mi], sbase + aLd + mi * (16 * D_ASTR) + ks * 32);
#pragma unroll
            for (int p = 0; p < 2; p++) {
                if (BL) ldsm4(bf[p], sbase + bLdNT + p * (16 * D_ASTR) + ks * 32);
                else    ldsm4t(bf[p], sbase + bLdNN + (uint32_t)ks * (16 * 272) + p * 32);
            }
#pragma unroll
            for (int mi = 0; mi < 4; mi++)
#pragma unroll
                for (int ni = 0; ni < 4; ni++) {
                    uint32_t b2[2] = { bf[ni >> 1][(ni & 1) * 2], bf[ni >> 1][(ni & 1) * 2 + 1] };
                    mma16(acc[mi][ni], af[mi], b2);
                }
        }
    }

    int g = lane >> 2, q = lane & 3;
    if (EPI == 3) {
#pragma unroll
        for (int mi = 0; mi < 4; mi++) {
            int r0 = bm + wm * 64 + mi * 16 + g;
            int r1 = r0 + 8;
            long o0 = (r0 < cnt) ? (long)g_dst[e * T_TOK + r0] : -1;
            long o1 = (r1 < cnt) ? (long)g_dst[e * T_TOK + r1] : -1;
#pragma unroll
            for (int ni = 0; ni < 4; ni++) {
                int cx = bn + wn * 32 + ni * 8 + 2 * q;
                if (o0 >= 0) {
                    float2 v = { acc[mi][ni][0], acc[mi][ni][1] };
                    *(float2*)&C[o0 * H_DIM + cx] = v;
                }
                if (o1 >= 0) {
                    float2 v = { acc[mi][ni][2], acc[mi][ni][3] };
                    *(float2*)&C[o1 * H_DIM + cx] = v;
                }
            }
        }
    } else {
#pragma unroll
        for (int mi = 0; mi < 4; mi++) {
            int r0 = bm + wm * 64 + mi * 16 + g;
            int r1 = r0 + 8;
#pragma unroll
            for (int ni = 0; ni < 4; ni++) {
                int cx = bn + wn * 32 + ni * 8 + 2 * q;
                {
                    float2 p0 = *(float2*)&g_par[(size_t)(2 * r0) * H_DIM + cx];
                    float2 p1 = *(float2*)&g_par[(size_t)(2 * r0 + 1) * H_DIM + cx];
                    float2 v = { acc[mi][ni][0] + p0.x + p1.x,
                                 acc[mi][ni][1] + p0.y + p1.y };
                    *(float2*)&C[(size_t)r0 * H_DIM + cx] = v;
                }
                {
                    float2 p0 = *(float2*)&g_par[(size_t)(2 * r1) * H_DIM + cx];
                    float2 p1 = *(float2*)&g_par[(size_t)(2 * r1 + 1) * H_DIM + cx];
                    float2 v = { acc[mi][ni][2] + p0.x + p1.x,
                                 acc[mi][ni][3] + p0.y + p1.y };
                    *(float2*)&C[(size_t)r1 * H_DIM + cx] = v;
                }
            }
        }
    }
}

// ---------------- launch ---------------------------------------------------------
extern "C" void kernel_launch(void* const* d_in, const int* in_sizes, int n_in,
                              void* d_out, int out_size) {
    const float* x      = (const float*)d_in[0];
    const float* gate_w = (const float*)d_in[1];
    const float* bias   = (const float*)d_in[2];
    const float* Wi     = (const float*)d_in[3];
    const float* Wo     = (const float*)d_in[4];
    const float* sWi    = (const float*)d_in[5];
    const float* sWo    = (const float*)d_in[6];
    float* out = (float*)d_out;

    __half *p_act, *p_as, *p_hx, *p_hwi, *p_hwo, *p_hswi, *p_hswo;
    float* p_par;
    cudaGetSymbolAddress((void**)&p_act,  g_act);
    cudaGetSymbolAddress((void**)&p_as,   g_as);
    cudaGetSymbolAddress((void**)&p_par,  g_par);
    cudaGetSymbolAddress((void**)&p_hx,   g_hx);
    cudaGetSymbolAddress((void**)&p_hwi,  g_hwi);
    cudaGetSymbolAddress((void**)&p_hwo,  g_hwo);
    cudaGetSymbolAddress((void**)&p_hswi, g_hswi);
    cudaGetSymbolAddress((void**)&p_hswo, g_hswo);

    const int SMEM_UP_NT = 3 * (U_ATILE + 2 * U_BT_NT);   // 92160
    const int SMEM_UP_NN = 3 * (U_ATILE + 2 * U_BT_NN);   // 82944
    const int SMEM_DN_NN = 3 * (D_ATILE + D_BT_NN);       // 56832
    const int SMEM_DN_NT = 3 * (D_ATILE + D_BT_NT);       // 61440

    cudaFuncSetAttribute(up_gemm<1, 1>, cudaFuncAttributeMaxDynamicSharedMemorySize, SMEM_UP_NT);
    cudaFuncSetAttribute(up_gemm<0, 2>, cudaFuncAttributeMaxDynamicSharedMemorySize, SMEM_UP_NN);
    cudaFuncSetAttribute(down_gemm<0, 3>, cudaFuncAttributeMaxDynamicSharedMemorySize, SMEM_DN_NN);
    cudaFuncSetAttribute(down_gemm<1, 4>, cudaFuncAttributeMaxDynamicSharedMemorySize, SMEM_DN_NT);

    zero_counts_kernel<<<1, 32>>>();
    gating_kernel<<<T_TOK / 8, 256>>>(x, gate_w, bias);

    f2h_all_kernel<<<(int)((N8_TOT + 255) / 256), 256>>>(x, Wi, Wo, sWi, sWo);

    // shared up + GLU -> g_as  (NT split-B)
    up_gemm<1, 1><<<dim3(I_DIM / 128, T_TOK / 128), 512, SMEM_UP_NT>>>(p_hx, p_hswi, p_as);
    // expert up + GLU*w -> g_act  (NN split-B, gather)
    up_gemm<0, 2><<<dim3(I_DIM / 128, T_TOK / 128, E_NUM), 512, SMEM_UP_NN>>>(p_hx, p_hwi, p_act);
    // expert down -> g_par (NN, scatter)
    down_gemm<0, 3><<<dim3(H_DIM / 128, T_TOK / 128, E_NUM), 256, SMEM_DN_NN>>>(p_act, p_hwo, p_par);
    // shared down + final add -> out (NT)
    down_gemm<1, 4><<<dim3(H_DIM / 128, T_TOK / 128), 256, SMEM_DN_NT>>>(p_as, p_hswo, out);
}